// round 3
// baseline (speedup 1.0000x reference)
#include <cuda_runtime.h>
#include <cstdint>

#define SIGMA_INV 10000.0f  // 1 / 1e-4

// factor = 1 - prob = 1 - sigmoid(-d/sigma)*mask
//        = mask ? sigmoid(d/sigma) : 1
__device__ __forceinline__ float blend_factor(float d, int face) {
    // sigmoid(d/sigma) = 1/(1+exp(-d/sigma))
    float s = __fdividef(1.0f, 1.0f + __expf(-d * SIGMA_INV));
    return (face >= 0) ? s : 1.0f;
}

__global__ void __launch_bounds__(256)
self_shader_kernel(const float* __restrict__ zbuf,
                   const float* __restrict__ dists,
                   const int* __restrict__ pix_to_face,
                   float* __restrict__ out,
                   int n_pix) {
    int tid = blockIdx.x * blockDim.x + threadIdx.x;
    int pix = tid >> 2;       // 4 threads per pixel
    int sub = tid & 3;        // which quarter of K=16
    if (pix >= n_pix) return;

    // dists: 16 floats per pixel; this thread takes floats [sub*4, sub*4+4)
    const float4* d4p = reinterpret_cast<const float4*>(dists);
    float4 d = d4p[(pix << 2) + sub];

    // pix_to_face: 16 int32 per pixel; this thread takes 4 of them (one int4)
    const int4* f4p = reinterpret_cast<const int4*>(pix_to_face);
    int4 f = f4p[(pix << 2) + sub];

    float prod = blend_factor(d.x, f.x)
               * blend_factor(d.y, f.y)
               * blend_factor(d.z, f.z)
               * blend_factor(d.w, f.w);

    // reduce product across the 4-lane group (lanes pix*4 .. pix*4+3 are
    // contiguous within the warp)
    prod *= __shfl_xor_sync(0xFFFFFFFFu, prod, 1);
    prod *= __shfl_xor_sync(0xFFFFFFFFu, prod, 2);

    if (sub == 0) {
        // Only channel 0 of zbuf is needed: scalar load -> 1 sector per pixel.
        float z = __ldg(&zbuf[(size_t)pix << 4]);
        float alpha = 1.0f - prod;
        reinterpret_cast<float4*>(out)[pix] = make_float4(z, z, z, alpha);
    }
}

extern "C" void kernel_launch(void* const* d_in, const int* in_sizes, int n_in,
                              void* d_out, int out_size) {
    const float* zbuf  = (const float*)d_in[0];
    const float* dists = (const float*)d_in[1];
    const int*   p2f   = (const int*)d_in[2];
    float*       out   = (float*)d_out;

    int n_pix = in_sizes[0] / 16;           // N*H*W
    long long threads_total = (long long)n_pix * 4;
    int block = 256;
    int grid = (int)((threads_total + block - 1) / block);

    self_shader_kernel<<<grid, block>>>(zbuf, dists, p2f, out, n_pix);
}

// round 4
// speedup vs baseline: 1.0082x; 1.0082x over previous
#include <cuda_runtime.h>
#include <cstdint>

#define SIGMA_INV 10000.0f  // 1 / 1e-4

// factor = 1 - prob = 1 - sigmoid(-d/sigma)*mask = mask ? sigmoid(d/sigma) : 1
__device__ __forceinline__ float blend_factor(float d, int face) {
    float s = __fdividef(1.0f, 1.0f + __expf(-d * SIGMA_INV));
    return (face >= 0) ? s : 1.0f;
}

__global__ void __launch_bounds__(256)
self_shader_kernel(const float* __restrict__ zbuf,
                   const float* __restrict__ dists,
                   const int* __restrict__ pix_to_face,
                   float* __restrict__ out,
                   int n_pix) {
    int pix = blockIdx.x * blockDim.x + threadIdx.x;
    if (pix >= n_pix) return;

    const float4* d4 = reinterpret_cast<const float4*>(dists) + ((size_t)pix << 2);
    const int4*   f4 = reinterpret_cast<const int4*>(pix_to_face) + ((size_t)pix << 2);

    // Front-batch all loads: 4x LDG.128 (dists) + 4x LDG.128 (faces) + 1x LDG.32 (z)
    float4 d0 = d4[0], d1 = d4[1], d2 = d4[2], d3 = d4[3];
    int4   f0 = f4[0], f1 = f4[1], f2 = f4[2], f3 = f4[3];
    float  z  = __ldg(&zbuf[(size_t)pix << 4]);   // channel 0 only: 1 line / pixel

    float prod = blend_factor(d0.x, f0.x) * blend_factor(d0.y, f0.y)
               * blend_factor(d0.z, f0.z) * blend_factor(d0.w, f0.w);
    prod *= blend_factor(d1.x, f1.x) * blend_factor(d1.y, f1.y)
          * blend_factor(d1.z, f1.z) * blend_factor(d1.w, f1.w);
    prod *= blend_factor(d2.x, f2.x) * blend_factor(d2.y, f2.y)
          * blend_factor(d2.z, f2.z) * blend_factor(d2.w, f2.w);
    prod *= blend_factor(d3.x, f3.x) * blend_factor(d3.y, f3.y)
          * blend_factor(d3.z, f3.z) * blend_factor(d3.w, f3.w);

    reinterpret_cast<float4*>(out)[pix] = make_float4(z, z, z, 1.0f - prod);
}

extern "C" void kernel_launch(void* const* d_in, const int* in_sizes, int n_in,
                              void* d_out, int out_size) {
    const float* zbuf  = (const float*)d_in[0];
    const float* dists = (const float*)d_in[1];
    const int*   p2f   = (const int*)d_in[2];
    float*       out   = (float*)d_out;

    int n_pix = in_sizes[0] / 16;   // N*H*W
    int block = 256;
    int grid = (n_pix + block - 1) / block;

    self_shader_kernel<<<grid, block>>>(zbuf, dists, p2f, out, n_pix);
}